// round 1
// baseline (speedup 1.0000x reference)
#include <cuda_runtime.h>

#define W      512
#define OUTW   502
#define TX     32
#define TY     32
#define HALO   10
#define TW     (TX + HALO)   // 42
#define TH     (TY + HALO)   // 42
#define KS     11
#define NPLANE 48            // 16 batch * 3 channels

__device__ double g_acc;

__global__ void zero_acc_kernel() { g_acc = 0.0; }

__global__ void finalize_kernel(float* out) {
    const double n = (double)NPLANE * (double)OUTW * (double)OUTW;
    out[0] = (float)(1.0 - g_acc / n);
}

__launch_bounds__(256)
__global__ void ssim_kernel(const float* __restrict__ X, const float* __restrict__ Y) {
    __shared__ float xs[TH][TW];
    __shared__ float ys[TH][TW];
    __shared__ float h0[TH][TX];
    __shared__ float h1[TH][TX];
    __shared__ float h2[TH][TX];
    __shared__ float h3[TH][TX];
    __shared__ float h4[TH][TX];
    __shared__ float warpsums[8];

    const int tid   = threadIdx.x;
    const int plane = blockIdx.z;
    const int c0    = blockIdx.x * TX;
    const int r0    = blockIdx.y * TY;

    const float* __restrict__ xp = X + (size_t)plane * W * W;
    const float* __restrict__ yp = Y + (size_t)plane * W * W;

    // Gaussian weights (fp32, matches reference numerics)
    float w[KS];
    {
        float s = 0.f;
        #pragma unroll
        for (int i = 0; i < KS; i++) {
            float d = (float)(i - (KS - 1) / 2);
            w[i] = expf(-d * d / (2.0f * 1.5f * 1.5f));
            s += w[i];
        }
        #pragma unroll
        for (int i = 0; i < KS; i++) w[i] /= s;
    }

    // ---- Load input tiles (coalesced, boundary-guarded) ----
    for (int idx = tid; idx < TH * TW; idx += 256) {
        int rr = idx / TW, cc = idx % TW;
        int gr = r0 + rr, gc = c0 + cc;
        float xv = 0.f, yv = 0.f;
        if (gr < W && gc < W) {
            xv = xp[gr * W + gc];
            yv = yp[gr * W + gc];
        }
        xs[rr][cc] = xv;
        ys[rr][cc] = yv;
    }
    __syncthreads();

    // ---- Horizontal blur of {x, y, x^2, y^2, xy} ----
    {
        const int col = tid & 31;
        for (int rr = tid >> 5; rr < TH; rr += 8) {
            float a0 = 0.f, a1 = 0.f, a2 = 0.f, a3 = 0.f, a4 = 0.f;
            #pragma unroll
            for (int k = 0; k < KS; k++) {
                float xv = xs[rr][col + k];
                float yv = ys[rr][col + k];
                float wk = w[k];
                a0 += wk * xv;
                a1 += wk * yv;
                a2 += wk * xv * xv;
                a3 += wk * yv * yv;
                a4 += wk * xv * yv;
            }
            h0[rr][col] = a0;
            h1[rr][col] = a1;
            h2[rr][col] = a2;
            h3[rr][col] = a3;
            h4[rr][col] = a4;
        }
    }
    __syncthreads();

    // ---- Vertical blur + SSIM map + local accumulate ----
    float acc = 0.f;
    {
        const int col = tid & 31;
        const int gc  = c0 + col;
        for (int oy = tid >> 5; oy < TY; oy += 8) {
            int gr = r0 + oy;
            if (gr < OUTW && gc < OUTW) {
                float m0 = 0.f, m1 = 0.f, m2 = 0.f, m3 = 0.f, m4 = 0.f;
                #pragma unroll
                for (int k = 0; k < KS; k++) {
                    float wk = w[k];
                    m0 += wk * h0[oy + k][col];
                    m1 += wk * h1[oy + k][col];
                    m2 += wk * h2[oy + k][col];
                    m3 += wk * h3[oy + k][col];
                    m4 += wk * h4[oy + k][col];
                }
                float mux2 = m0 * m0;
                float muy2 = m1 * m1;
                float muxy = m0 * m1;
                float varx = m2 - mux2;
                float vary = m3 - muy2;
                float cov  = m4 - muxy;
                const float C1 = 1e-4f;   // 0.01^2
                const float C2 = 9e-4f;   // 0.03^2
                float num = (2.f * muxy + C1) * (2.f * cov + C2);
                float den = (mux2 + muy2 + C1) * (varx + vary + C2);
                acc += num / den;
            }
        }
    }

    // ---- Block reduction -> one double atomic per block ----
    #pragma unroll
    for (int off = 16; off > 0; off >>= 1)
        acc += __shfl_down_sync(0xffffffffu, acc, off);
    if ((tid & 31) == 0) warpsums[tid >> 5] = acc;
    __syncthreads();
    if (tid < 8) {
        float v = warpsums[tid];
        #pragma unroll
        for (int off = 4; off > 0; off >>= 1)
            v += __shfl_down_sync(0xffu, v, off);
        if (tid == 0) atomicAdd(&g_acc, (double)v);
    }
}

extern "C" void kernel_launch(void* const* d_in, const int* in_sizes, int n_in,
                              void* d_out, int out_size) {
    const float* x = (const float*)d_in[0];
    const float* y = (const float*)d_in[1];
    float* out = (float*)d_out;

    zero_acc_kernel<<<1, 1>>>();
    dim3 grid((OUTW + TX - 1) / TX, (OUTW + TY - 1) / TY, NPLANE);  // 16 x 16 x 48
    ssim_kernel<<<grid, 256>>>(x, y);
    finalize_kernel<<<1, 1>>>(out);
}